// round 17
// baseline (speedup 1.0000x reference)
#include <cuda_runtime.h>
#include <mma.h>

using namespace nvcuda;

#define BSZ 256
#define SLEN 64
#define HDIM 512
#define H2D 1024
#define VDIM 32000
#define NROWS (BSZ * SLEN) /* 16384 */

// ---------------- device scratch (static, no allocations) ----------------
__device__ float d_E[(size_t)NROWS * HDIM];         // embeddings (tf32-rounded)
__device__ float d_Gfb[(size_t)NROWS * 8 * HDIM];   // fwd|bwd input preacts [sample][4096]
__device__ float d_CombIn[(size_t)NROWS * H2D];     // [hf | hb] per (t,b), rounded
__device__ float d_Gc[(size_t)NROWS * 4 * H2D];     // combiner input preacts [sample][4096]
__device__ float d_h[2][2][BSZ * HDIM];             // [dir][parity], rounded
__device__ float d_cfb[2][BSZ * HDIM];              // [dir], fp32
__device__ float d_hcb[2][BSZ * H2D];               // combiner h [parity], rounded
__device__ float d_cc[BSZ * H2D];                   // fp32
__device__ float d_WihFBr[(size_t)8 * HDIM * HDIM]; // [WihF; WihB] rounded (4096 x 512)
__device__ float d_WihCr[(size_t)4 * H2D * H2D];
__device__ float d_WhhFr[4 * HDIM * HDIM];
__device__ float d_WhhBr[4 * HDIM * HDIM];
__device__ float d_WhhCr[(size_t)4 * H2D * H2D];
__device__ float d_Woutr[(size_t)VDIM * H2D];       // rounded Wout (32000 x 1024)

// round-to-nearest-even into tf32 (10 explicit mantissa bits)
__device__ __forceinline__ float t32(float x) {
    unsigned u = __float_as_uint(x);
    unsigned r = (u + 0xFFFu + ((u >> 13) & 1u)) & 0xFFFFE000u;
    return __uint_as_float(r);
}
__device__ __forceinline__ float sigm(float x) { return 1.f / (1.f + __expf(-x)); }

__device__ __forceinline__ void cp16(void* dst, const void* src) {
    unsigned d = (unsigned)__cvta_generic_to_shared(dst);
    asm volatile("cp.async.cg.shared.global [%0], [%1], 16;" ::"r"(d), "l"(src));
}
__device__ __forceinline__ void cp_commit() { asm volatile("cp.async.commit_group;"); }
template <int N>
__device__ __forceinline__ void cp_wait() { asm volatile("cp.async.wait_group %0;" ::"n"(N)); }

// ---- mbarrier + bulk-copy helpers (sm_90+; valid on sm_103a) ----
__device__ __forceinline__ void mbar_init(unsigned bar, unsigned cnt) {
    asm volatile("mbarrier.init.shared.b64 [%0], %1;" ::"r"(bar), "r"(cnt) : "memory");
}
__device__ __forceinline__ void mbar_expect_tx(unsigned bar, unsigned bytes) {
    asm volatile("mbarrier.arrive.expect_tx.shared.b64 _, [%0], %1;" ::"r"(bar), "r"(bytes)
                 : "memory");
}
__device__ __forceinline__ void bulk_cp(unsigned dst, const void* src, unsigned bytes,
                                        unsigned bar) {
    asm volatile(
        "cp.async.bulk.shared::cta.global.mbarrier::complete_tx::bytes [%0], [%1], %2, [%3];"
        ::"r"(dst), "l"(src), "r"(bytes), "r"(bar)
        : "memory");
}
__device__ __forceinline__ void mbar_wait(unsigned bar, unsigned parity) {
    asm volatile(
        "{\n\t"
        ".reg .pred P1;\n\t"
        "WAIT_LOOP_%=:\n\t"
        "mbarrier.try_wait.parity.acquire.cta.shared::cta.b64 P1, [%0], %1, 0x989680;\n\t"
        "@P1 bra.uni WAIT_DONE_%=;\n\t"
        "bra.uni WAIT_LOOP_%=;\n\t"
        "WAIT_DONE_%=:\n\t"
        "}"
        ::"r"(bar), "r"(parity)
        : "memory");
}

// ---------------- fused prep: all weight roundings + state inits in ONE launch ------------
// block = 1024 floats (256 threads x 1 float4)
__global__ void __launch_bounds__(256) prep_kernel(
    const float* __restrict__ WihF, const float* __restrict__ WihB,
    const float* __restrict__ WhhF, const float* __restrict__ WhhB,
    const float* __restrict__ WihC, const float* __restrict__ WhhC,
    const float* __restrict__ Wout,
    const float* __restrict__ h0f, const float* __restrict__ h0b, const float* __restrict__ h0c,
    const float* __restrict__ c0f, const float* __restrict__ c0b, const float* __restrict__ c0c) {
    int blk = blockIdx.x;
    const float* src;
    float* dst;
    int base;
    bool doround = true;
    if (blk < 1024)        { src = WihF; dst = d_WihFBr; base = blk; }
    else if (blk < 2048)   { src = WihB; dst = d_WihFBr + 1048576; base = blk - 1024; }
    else if (blk < 3072)   { src = WhhF; dst = d_WhhFr; base = blk - 2048; }
    else if (blk < 4096)   { src = WhhB; dst = d_WhhBr; base = blk - 3072; }
    else if (blk < 8192)   { src = WihC; dst = d_WihCr; base = blk - 4096; }
    else if (blk < 12288)  { src = WhhC; dst = d_WhhCr; base = blk - 8192; }
    else if (blk < 44288)  { src = Wout; dst = d_Woutr; base = blk - 12288; }
    else if (blk < 44416)  { src = h0f; dst = d_h[0][0]; base = blk - 44288; }
    else if (blk < 44544)  { src = h0b; dst = d_h[1][0]; base = blk - 44416; }
    else if (blk < 44800)  { src = h0c; dst = d_hcb[0]; base = blk - 44544; }
    else if (blk < 44928)  { src = c0f; dst = d_cfb[0]; base = blk - 44800; doround = false; }
    else if (blk < 45056)  { src = c0b; dst = d_cfb[1]; base = blk - 44928; doround = false; }
    else                   { src = c0c; dst = d_cc;     base = blk - 45056; doround = false; }
    size_t i = (size_t)base * 256 + threadIdx.x;
    float4 v = ((const float4*)src)[i];
    if (doround) { v.x = t32(v.x); v.y = t32(v.y); v.z = t32(v.z); v.w = t32(v.w); }
    ((float4*)dst)[i] = v;
}

__global__ void embed_kernel(const int* __restrict__ x, const float* __restrict__ Wemb) {
    int r = blockIdx.x;
    int tok = x[r];
    float4* dst = (float4*)(d_E + (size_t)r * HDIM);
    if (tok == 0) {
        float4 z = {0.f, 0.f, 0.f, 0.f};
        dst[threadIdx.x] = z;
    } else {
        float4 v = ((const float4*)(Wemb + (size_t)tok * HDIM))[threadIdx.x];
        v.x = t32(v.x); v.y = t32(v.y); v.z = t32(v.z); v.w = t32(v.w);
        dst[threadIdx.x] = v;
    }
}

// ---------------- TF32 GEMM, 128x256 block tile, warp tile 64x64, BK=32 ----------------
// C[M,N] = A[M,K] @ W[N,K]^T. 256 threads (8 warps as 2m x 4n). Double-buffered cp.async.
// smem: As[2][128][36] + Bs[2][256][36] = 110592 B -> 1 CTA/SM.
__global__ void __launch_bounds__(256) gemm_pre(const float* __restrict__ A,
                                                const float* __restrict__ W,
                                                float* __restrict__ C,
                                                int M, int N, int K) {
    extern __shared__ float sm[];
    float* As = sm;                 // [2][128][36]
    float* Bs = sm + 2 * 128 * 36;  // [2][256][36]
    const int m0 = blockIdx.y * 128, n0 = blockIdx.x * 256;
    const int tid = threadIdx.x;
    const int w = tid >> 5, wm = w >> 2, wn = w & 3;
    const int KT = K >> 5;

    wmma::fragment<wmma::accumulator, 16, 16, 8, float> cf[4][4];
#pragma unroll
    for (int i = 0; i < 4; i++)
#pragma unroll
        for (int j = 0; j < 4; j++) wmma::fill_fragment(cf[i][j], 0.f);

    {
#pragma unroll
        for (int i = 0; i < 4; i++) {
            int lin = tid + i * 256;
            int r = lin >> 3, c4 = (lin & 7) * 4;
            cp16(As + r * 36 + c4, A + (size_t)(m0 + r) * K + c4);
        }
#pragma unroll
        for (int i = 0; i < 8; i++) {
            int lin = tid + i * 256;
            int r = lin >> 3, c4 = (lin & 7) * 4;
            cp16(Bs + r * 36 + c4, W + (size_t)(n0 + r) * K + c4);
        }
        cp_commit();
    }
    int buf = 0;
#pragma unroll 1
    for (int kt = 0; kt < KT; kt++) {
        cp_wait<0>();
        __syncthreads();
        if (kt + 1 < KT) {
            int nb = buf ^ 1;
#pragma unroll
            for (int i = 0; i < 4; i++) {
                int lin = tid + i * 256;
                int r = lin >> 3, c4 = (lin & 7) * 4;
                cp16(As + nb * 4608 + r * 36 + c4, A + (size_t)(m0 + r) * K + (kt + 1) * 32 + c4);
            }
#pragma unroll
            for (int i = 0; i < 8; i++) {
                int lin = tid + i * 256;
                int r = lin >> 3, c4 = (lin & 7) * 4;
                cp16(Bs + nb * 9216 + r * 36 + c4, W + (size_t)(n0 + r) * K + (kt + 1) * 32 + c4);
            }
            cp_commit();
        }
#pragma unroll
        for (int ks = 0; ks < 4; ks++) {
            wmma::fragment<wmma::matrix_a, 16, 16, 8, wmma::precision::tf32, wmma::row_major> af[4];
            wmma::fragment<wmma::matrix_b, 16, 16, 8, wmma::precision::tf32, wmma::col_major> bf[4];
#pragma unroll
            for (int i = 0; i < 4; i++)
                wmma::load_matrix_sync(af[i], As + buf * 4608 + (wm * 64 + i * 16) * 36 + ks * 8, 36);
#pragma unroll
            for (int j = 0; j < 4; j++)
                wmma::load_matrix_sync(bf[j], Bs + buf * 9216 + (wn * 64 + j * 16) * 36 + ks * 8, 36);
#pragma unroll
            for (int i = 0; i < 4; i++)
#pragma unroll
                for (int j = 0; j < 4; j++) wmma::mma_sync(cf[i][j], af[i], bf[j], cf[i][j]);
        }
        buf ^= 1;
    }
#pragma unroll
    for (int i = 0; i < 4; i++)
#pragma unroll
        for (int j = 0; j < 4; j++)
            wmma::store_matrix_sync(C + (size_t)(m0 + wm * 64 + i * 16) * N + n0 + wn * 64 + j * 16,
                                    cf[i][j], N, wmma::mem_row_major);
}

// ---------------- LSTM step fwd+bwd: BULK-COPY pipeline, BK=128, M=64 tile ----------------
// grid (4, 16, 2) = 128 blocks (1 wave). 256 threads, warps 2(m) x 4(n), cf[2][2].
// smem: As[2][64][132] + Bs[2][128][132] + 2 mbarriers = 202768 B  (1 CTA/SM)
#define STEP_SMEM (2 * 64 * 132 * 4 + 2 * 128 * 132 * 4 + 16)
__global__ void __launch_bounds__(256) lstm_step_fb(
    const float* __restrict__ WhhF, const float* __restrict__ WhhB,
    const float* __restrict__ biF, const float* __restrict__ bhF,
    const float* __restrict__ biB, const float* __restrict__ bhB, int t) {
    extern __shared__ float sm[];
    float* As = sm;                    // [2][64][132]
    float* Bs = sm + 2 * 64 * 132;     // [2][128][132]
    float* gbuf = sm;                  // overlay [64][132] (== As stage 0)
    const unsigned smb = (unsigned)__cvta_generic_to_shared(sm);
    const unsigned barb = smb + (2 * 64 * 132 + 2 * 128 * 132) * 4;

    const int dir = blockIdx.z;
    const float* Whh = dir ? WhhB : WhhF;
    const float* bi = dir ? biB : biF;
    const float* bh = dir ? bhB : bhF;
    const float* hprev = d_h[dir][t & 1];
    float* hnext = d_h[dir][(t + 1) & 1];
    float* cst = d_cfb[dir];
    const int grow0 = (dir ? (SLEN - 1 - t) : t) * BSZ;

    const int m0 = blockIdx.x * 64;
    const int j0 = blockIdx.y * 32;
    const int tid = threadIdx.x;
    const int w = tid >> 5, wm = w >> 2, wn = w & 3;

    // hoisted epilogue operand loads (G from merged d_Gfb: row stride 4096, bwd half at +2048)
    float gpre[8][4], cpre[8], bsum[8][4];
#pragma unroll
    for (int p = 0; p < 8; p++) {
        int idx = p * 256 + tid;
        int m = idx >> 5, jj = idx & 31;
        int b = m0 + m, j = j0 + jj;
        const float* grow = d_Gfb + (size_t)(grow0 + b) * (8 * HDIM) + dir * (4 * HDIM);
        gpre[p][0] = grow[j];
        gpre[p][1] = grow[HDIM + j];
        gpre[p][2] = grow[2 * HDIM + j];
        gpre[p][3] = grow[3 * HDIM + j];
        cpre[p] = cst[(size_t)b * HDIM + j];
        bsum[p][0] = bi[j] + bh[j];
        bsum[p][1] = bi[HDIM + j] + bh[HDIM + j];
        bsum[p][2] = bi[2 * HDIM + j] + bh[2 * HDIM + j];
        bsum[p][3] = bi[3 * HDIM + j] + bh[3 * HDIM + j];
    }

    if (tid == 0) {
        mbar_init(barb, 192);
        mbar_init(barb + 8, 192);
    }
    __syncthreads();

    const float* srcRow = nullptr;
    unsigned dstBase = 0;
    if (tid < 128) {  // B row
        int gr = (tid >> 5) * HDIM + j0 + (tid & 31);
        srcRow = Whh + (size_t)gr * HDIM;
        dstBase = smb + (2 * 64 * 132 + tid * 132) * 4;
    } else if (tid < 192) {  // A row
        int r = tid - 128;
        srcRow = hprev + (size_t)(m0 + r) * HDIM;
        dstBase = smb + (r * 132) * 4;
    }
    const unsigned stageOffB = 128 * 132 * 4;
    const unsigned stageOffA = 64 * 132 * 4;
    const unsigned myStageOff = (tid < 128) ? stageOffB : stageOffA;

    wmma::fragment<wmma::accumulator, 16, 16, 8, float> cf[2][2];
#pragma unroll
    for (int i = 0; i < 2; i++)
#pragma unroll
        for (int j = 0; j < 2; j++) wmma::fill_fragment(cf[i][j], 0.f);

    if (tid < 192) {
        mbar_expect_tx(barb, 512);
        bulk_cp(dstBase, srcRow, 512, barb);
    }
#pragma unroll 1
    for (int kt = 0; kt < 4; kt++) {  // K = 512, BK = 128
        int st = kt & 1;
        mbar_wait(barb + 8 * st, (kt >> 1) & 1);
        __syncthreads();
        if (kt < 3 && tid < 192) {
            int ns = (kt + 1) & 1;
            unsigned nbar = barb + 8 * ns;
            mbar_expect_tx(nbar, 512);
            bulk_cp(dstBase + ns * myStageOff, srcRow + (kt + 1) * 128, 512, nbar);
        }
#pragma unroll
        for (int ks = 0; ks < 16; ks++) {
            wmma::fragment<wmma::matrix_a, 16, 16, 8, wmma::precision::tf32, wmma::row_major> af[2];
            wmma::fragment<wmma::matrix_b, 16, 16, 8, wmma::precision::tf32, wmma::col_major> bf[2];
#pragma unroll
            for (int i = 0; i < 2; i++)
                wmma::load_matrix_sync(af[i], As + st * 64 * 132 + (wm * 32 + i * 16) * 132 + ks * 8,
                                       132);
#pragma unroll
            for (int j = 0; j < 2; j++)
                wmma::load_matrix_sync(bf[j],
                                       Bs + st * 128 * 132 + (wn * 32 + j * 16) * 132 + ks * 8, 132);
#pragma unroll
            for (int i = 0; i < 2; i++)
#pragma unroll
                for (int j = 0; j < 2; j++) wmma::mma_sync(cf[i][j], af[i], bf[j], cf[i][j]);
        }
    }
    __syncthreads();
#pragma unroll
    for (int i = 0; i < 2; i++)
#pragma unroll
        for (int j = 0; j < 2; j++)
            wmma::store_matrix_sync(gbuf + (wm * 32 + i * 16) * 132 + wn * 32 + j * 16, cf[i][j],
                                    132, wmma::mem_row_major);
    __syncthreads();

#pragma unroll
    for (int p = 0; p < 8; p++) {  // 64x32 cell elements
        int idx = p * 256 + tid;
        int m = idx >> 5, jj = idx & 31;
        int b = m0 + m, j = j0 + jj;
        float ip = gbuf[m * 132 + jj]      + gpre[p][0] + bsum[p][0];
        float fp = gbuf[m * 132 + 32 + jj] + gpre[p][1] + bsum[p][1];
        float gp = gbuf[m * 132 + 64 + jj] + gpre[p][2] + bsum[p][2];
        float op = gbuf[m * 132 + 96 + jj] + gpre[p][3] + bsum[p][3];
        float cn = sigm(fp) * cpre[p] + sigm(ip) * tanhf(gp);
        cst[(size_t)b * HDIM + j] = cn;
        float hr = t32(sigm(op) * tanhf(cn));
        hnext[(size_t)b * HDIM + j] = hr;
        d_CombIn[(size_t)(t * BSZ + b) * H2D + dir * HDIM + j] = hr;
    }
}

// ---------------- combiner LSTM step (H=1024): BULK-COPY pipeline, BK=128, M=64 ----------
// grid (4, 32) = 128 blocks (1 wave).
__global__ void __launch_bounds__(256) lstm_step_c(
    const float* __restrict__ Whh, const float* __restrict__ bi,
    const float* __restrict__ bh, int t) {
    extern __shared__ float sm[];
    float* As = sm;
    float* Bs = sm + 2 * 64 * 132;
    float* gbuf = sm;
    const unsigned smb = (unsigned)__cvta_generic_to_shared(sm);
    const unsigned barb = smb + (2 * 64 * 132 + 2 * 128 * 132) * 4;

    const float* hprev = d_hcb[t & 1];
    float* hnext = d_hcb[(t + 1) & 1];
    const int grow0 = t * BSZ;

    const int m0 = blockIdx.x * 64;
    const int j0 = blockIdx.y * 32;
    const int tid = threadIdx.x;
    const int w = tid >> 5, wm = w >> 2, wn = w & 3;

    float gpre[8][4], cpre[8], bsum[8][4];
#pragma unroll
    for (int p = 0; p < 8; p++) {
        int idx = p * 256 + tid;
        int m = idx >> 5, jj = idx & 31;
        int b = m0 + m, j = j0 + jj;
        const float* grow = d_Gc + (size_t)(grow0 + b) * (4 * H2D);
        gpre[p][0] = grow[j];
        gpre[p][1] = grow[H2D + j];
        gpre[p][2] = grow[2 * H2D + j];
        gpre[p][3] = grow[3 * H2D + j];
        cpre[p] = d_cc[(size_t)b * H2D + j];
        bsum[p][0] = bi[j] + bh[j];
        bsum[p][1] = bi[H2D + j] + bh[H2D + j];
        bsum[p][2] = bi[2 * H2D + j] + bh[2 * H2D + j];
        bsum[p][3] = bi[3 * H2D + j] + bh[3 * H2D + j];
    }

    if (tid == 0) {
        mbar_init(barb, 192);
        mbar_init(barb + 8, 192);
    }
    __syncthreads();

    const float* srcRow = nullptr;
    unsigned dstBase = 0;
    if (tid < 128) {
        int gr = (tid >> 5) * H2D + j0 + (tid & 31);
        srcRow = Whh + (size_t)gr * H2D;
        dstBase = smb + (2 * 64 * 132 + tid * 132) * 4;
    } else if (tid < 192) {
        int r = tid - 128;
        srcRow = hprev + (size_t)(m0 + r) * H2D;
        dstBase = smb + (r * 132) * 4;
    }
    const unsigned stageOffB = 128 * 132 * 4;
    const unsigned stageOffA = 64 * 132 * 4;
    const unsigned myStageOff = (tid < 128) ? stageOffB : stageOffA;

    wmma::fragment<wmma::accumulator, 16, 16, 8, float> cf[2][2];
#pragma unroll
    for (int i = 0; i < 2; i++)
#pragma unroll
        for (int j = 0; j < 2; j++) wmma::fill_fragment(cf[i][j], 0.f);

    if (tid < 192) {
        mbar_expect_tx(barb, 512);
        bulk_cp(dstBase, srcRow, 512, barb);
    }
#pragma unroll 1
    for (int kt = 0; kt < 8; kt++) {  // K = 1024, BK = 128
        int st = kt & 1;
        mbar_wait(barb + 8 * st, (kt >> 1) & 1);
        __syncthreads();
        if (kt < 7 && tid < 192) {
            int ns = (kt + 1) & 1;
            unsigned nbar = barb + 8 * ns;
            mbar_expect_tx(nbar, 512);
            bulk_cp(dstBase + ns * myStageOff, srcRow + (kt + 1) * 128, 512, nbar);
        }
#pragma unroll
        for (int ks = 0; ks < 16; ks++) {
            wmma::fragment<wmma::matrix_a, 16, 16, 8, wmma::precision::tf32, wmma::row_major> af[2];
            wmma::fragment<wmma::matrix_b, 16, 16, 8, wmma::precision::tf32, wmma::col_major> bf[2];
#pragma unroll
            for (int i = 0; i < 2; i++)
                wmma::load_matrix_sync(af[i], As + st * 64 * 132 + (wm * 32 + i * 16) * 132 + ks * 8,
                                       132);
#pragma unroll
            for (int j = 0; j < 2; j++)
                wmma::load_matrix_sync(bf[j],
                                       Bs + st * 128 * 132 + (wn * 32 + j * 16) * 132 + ks * 8, 132);
#pragma unroll
            for (int i = 0; i < 2; i++)
#pragma unroll
                for (int j = 0; j < 2; j++) wmma::mma_sync(cf[i][j], af[i], bf[j], cf[i][j]);
        }
    }
    __syncthreads();
#pragma unroll
    for (int i = 0; i < 2; i++)
#pragma unroll
        for (int j = 0; j < 2; j++)
            wmma::store_matrix_sync(gbuf + (wm * 32 + i * 16) * 132 + wn * 32 + j * 16, cf[i][j],
                                    132, wmma::mem_row_major);
    __syncthreads();

#pragma unroll
    for (int p = 0; p < 8; p++) {
        int idx = p * 256 + tid;
        int m = idx >> 5, jj = idx & 31;
        int b = m0 + m, j = j0 + jj;
        float ip = gbuf[m * 132 + jj]      + gpre[p][0] + bsum[p][0];
        float fp = gbuf[m * 132 + 32 + jj] + gpre[p][1] + bsum[p][1];
        float gp = gbuf[m * 132 + 64 + jj] + gpre[p][2] + bsum[p][2];
        float op = gbuf[m * 132 + 96 + jj] + gpre[p][3] + bsum[p][3];
        float cn = sigm(fp) * cpre[p] + sigm(ip) * tanhf(gp);
        d_cc[(size_t)b * H2D + j] = cn;
        float hn = sigm(op) * tanhf(cn);
        hnext[(size_t)b * H2D + j] = t32(hn);
    }
}

__global__ void bias_add_kernel(float* __restrict__ C, const float* __restrict__ bout) {
    size_t idx = (size_t)blockIdx.x * 256 + threadIdx.x;
    float4 v = ((float4*)C)[idx];
    int n = (int)(idx % (VDIM / 4)) * 4;
    v.x += bout[n]; v.y += bout[n + 1]; v.z += bout[n + 2]; v.w += bout[n + 3];
    ((float4*)C)[idx] = v;
}

// ---------------- host orchestration (single stream) ----------------
extern "C" void kernel_launch(void* const* d_in, const int* in_sizes, int n_in,
                              void* d_out, int out_size) {
    (void)in_sizes; (void)n_in; (void)out_size;
    const int* x = (const int*)d_in[0];
    const float* Wemb = (const float*)d_in[1];
    const float* WihF = (const float*)d_in[2];
    const float* WhhF = (const float*)d_in[3];
    const float* biF = (const float*)d_in[4];
    const float* bhF = (const float*)d_in[5];
    const float* WihB = (const float*)d_in[6];
    const float* WhhB = (const float*)d_in[7];
    const float* biB = (const float*)d_in[8];
    const float* bhB = (const float*)d_in[9];
    const float* WihC = (const float*)d_in[10];
    const float* WhhC = (const float*)d_in[11];
    const float* biC = (const float*)d_in[12];
    const float* bhC = (const float*)d_in[13];
    const float* Wout = (const float*)d_in[14];
    const float* bout = (const float*)d_in[15];
    const float* h0f = (const float*)d_in[16];
    const float* c0f = (const float*)d_in[17];
    const float* h0b = (const float*)d_in[18];
    const float* c0b = (const float*)d_in[19];
    const float* h0c = (const float*)d_in[20];
    const float* c0c = (const float*)d_in[21];
    float* out = (float*)d_out;

    void *pE, *pGfb, *pCI, *pGc, *phc;
    void *pWiFB, *pWiC, *pWhF, *pWhB, *pWhC, *pWo;
    cudaGetSymbolAddress(&pE, d_E);
    cudaGetSymbolAddress(&pGfb, d_Gfb);
    cudaGetSymbolAddress(&pCI, d_CombIn);
    cudaGetSymbolAddress(&pGc, d_Gc);
    cudaGetSymbolAddress(&phc, d_hcb);   // [0] = final combiner h (rounded)
    cudaGetSymbolAddress(&pWiFB, d_WihFBr);
    cudaGetSymbolAddress(&pWiC, d_WihCr);
    cudaGetSymbolAddress(&pWhF, d_WhhFr);
    cudaGetSymbolAddress(&pWhB, d_WhhBr);
    cudaGetSymbolAddress(&pWhC, d_WhhCr);
    cudaGetSymbolAddress(&pWo, d_Woutr);

    cudaFuncSetAttribute(gemm_pre, cudaFuncAttributeMaxDynamicSharedMemorySize, 110592);
    cudaFuncSetAttribute(lstm_step_fb, cudaFuncAttributeMaxDynamicSharedMemorySize, STEP_SMEM);
    cudaFuncSetAttribute(lstm_step_c, cudaFuncAttributeMaxDynamicSharedMemorySize, STEP_SMEM);

    // launch 0: fused prep (incl. Wout rounding); launch 1: embedding
    prep_kernel<<<45312, 256>>>(WihF, WihB, WhhF, WhhB, WihC, WhhC, Wout,
                                h0f, h0b, h0c, c0f, c0b, c0c);
    embed_kernel<<<NROWS, 128>>>(x, Wemb);
    // merged fwd+bwd input projection: Gfb[sample][4096] = E @ [WihF;WihB]^T
    gemm_pre<<<dim3((8 * HDIM) / 256, NROWS / 128), 256, 110592>>>(
        (const float*)pE, (const float*)pWiFB, (float*)pGfb, NROWS, 8 * HDIM, HDIM);
    // fwd + bwd recurrence, bulk-copy step kernels (1 wave of 128 blocks each)
    for (int t = 0; t < SLEN; t++)
        lstm_step_fb<<<dim3(BSZ / 64, HDIM / 32, 2), 256, STEP_SMEM>>>(
            (const float*)pWhF, (const float*)pWhB, biF, bhF, biB, bhB, t);
    // combiner input projection + recurrence
    gemm_pre<<<dim3((4 * H2D) / 256, NROWS / 128), 256, 110592>>>(
        (const float*)pCI, (const float*)pWiC, (float*)pGc, NROWS, 4 * H2D, H2D);
    for (int t = 0; t < SLEN; t++)
        lstm_step_c<<<dim3(BSZ / 64, H2D / 32), 256, STEP_SMEM>>>(
            (const float*)pWhC, biC, bhC, t);
    // output head: single-pass TF32 GEMM on rounded operands + bias
    gemm_pre<<<dim3(VDIM / 256, BSZ / 128), 256, 110592>>>(
        (const float*)phc, (const float*)pWo, out, BSZ, VDIM, H2D);
    bias_add_kernel<<<(BSZ * VDIM / 4) / 256, 256>>>(out, bout);
}